// round 17
// baseline (speedup 1.0000x reference)
#include <cuda_runtime.h>
#include <cuda_fp16.h>
#include <cstdint>

// ---------------------------------------------------------------------------
// out[8192,4096] = x[8192,4096]_fp32 @ sign(fp16(w[4096,4096]))
//
// R17: overlap the x-convert with the GEMM.
//  - GEMM CTA = 17 warps: warps 0-15 run the R12 GEMM (unchanged, the
//    measured HMMA issue wall); warp 16 converts x->fp16 via global
//    work-steal in k-ascending order and publishes per-k-chunk ready flags.
//  - load_stage(kt) gates on chunk kt's flag (elected ld.acquire poll).
//  - w-convert (needs transpose) stays as a small pre-kernel; flags reset
//    by cudaMemsetAsync each call (no cross-call caching).
// ---------------------------------------------------------------------------

#define M_DIM 8192
#define N_DIM 4096
#define K_DIM 4096

#define BM 128
#define BN 256
#define BK 64
#define STAGES 4
#define GEMM_THREADS 512
#define THREADS_ALL  544           // 16 GEMM warps + 1 convert warp
#define GEMM_WARPS   16
#define NKI (K_DIM / BK)           // 64

#define A_TILE_BYTES (BM * BK * 2)            // 16384
#define B_TILE_BYTES (BN * BK * 2)            // 32768
#define STAGE_BYTES  (A_TILE_BYTES + B_TILE_BYTES)   // 49152
#define SMEM_DYN     (1024 + 1024 + STAGES * STAGE_BYTES)  // 198656

// x-convert work items: 8192 items of (64 rows x 64 k); 128 items per k-chunk
#define X_ITEMS        8192
#define ITEMS_PER_CHK  128

// ------------------------------ scratch -----------------------------------
__device__ __align__(1024) __half g_xh[(size_t)M_DIM * K_DIM];   // 64 MB
__device__ __align__(1024) __half g_wbt[(size_t)N_DIM * K_DIM];  // 32 MB
__device__ int g_flags[1 + NKI];   // [0]=work-steal counter, [1+c]=chunk cnt

// --------------------------- w convert kernel ------------------------------
// w[K,N] fp32 -> wbt[N,K] fp16 sign(fp16(w)); 64x64 tiles, vectorized IO
__global__ void __launch_bounds__(256, 4) cvt_w_kernel(
    const float* __restrict__ w, __half* __restrict__ wbt)
{
    __shared__ __half t[64][72];
    const int n0 = blockIdx.x * 64;
    const int k0 = blockIdx.y * 64;
    const int tid = threadIdx.x;

    const int lk = tid >> 4;
    const int ln = (tid & 15) << 2;
    #pragma unroll
    for (int i = 0; i < 4; i++) {
        int k = lk + i * 16;
        float4 v = *reinterpret_cast<const float4*>(
            w + (size_t)(k0 + k) * N_DIM + n0 + ln);
        float f[4] = {v.x, v.y, v.z, v.w};
        #pragma unroll
        for (int j = 0; j < 4; j++) {
            __half h = __float2half_rn(f[j]);
            uint16_t hb = *reinterpret_cast<uint16_t*>(&h);
            uint16_t sb = (uint16_t)((hb & 0x7FFF) ? ((hb & 0x8000) | 0x3C00) : 0);
            t[ln + j][k] = *reinterpret_cast<__half*>(&sb);
        }
    }
    __syncthreads();

    const int sn = tid >> 2;
    const int sk = (tid & 3) << 3;
    #pragma unroll
    for (int i = 0; i < 2; i++) {
        int kk = sk + i * 32;
        uint4 o = *reinterpret_cast<uint4*>(&t[sn][kk]);
        *reinterpret_cast<uint4*>(
            wbt + (size_t)(n0 + sn) * K_DIM + k0 + kk) = o;
    }
}

// ------------------------------ PTX helpers -------------------------------
__device__ __forceinline__ uint32_t smem_u32(const void* p) {
    uint32_t a;
    asm("{ .reg .u64 t; cvta.to.shared.u64 t, %1; cvt.u32.u64 %0, t; }"
        : "=r"(a) : "l"(p));
    return a;
}

__device__ __forceinline__ uint32_t elect_one() {
    uint32_t pred;
    asm volatile(
        "{\n\t.reg .pred p;\n\t"
        "elect.sync _|p, 0xFFFFFFFF;\n\t"
        "selp.b32 %0, 1, 0, p;\n\t}"
        : "=r"(pred));
    return pred;
}

__device__ __forceinline__ uint32_t ld_acquire_gpu(const int* p) {
    uint32_t v;
    asm volatile("ld.acquire.gpu.global.u32 %0, [%1];" : "=r"(v) : "l"(p) : "memory");
    return v;
}

__device__ __forceinline__ void cp_async_16(uint32_t smem_dst, const void* gmem_src) {
    asm volatile("cp.async.cg.shared.global [%0], [%1], 16;"
                 :: "r"(smem_dst), "l"(gmem_src));
}

#define MBARRIER_INIT(addr, count) \
    asm volatile("mbarrier.init.shared.b64 [%0], %1;" \
                 :: "r"((uint32_t)(addr)), "r"((uint32_t)(count)) : "memory")

#define MBARRIER_ARRIVE(addr) \
    asm volatile("mbarrier.arrive.shared.b64 _, [%0];" \
                 :: "r"((uint32_t)(addr)) : "memory")

#define CPASYNC_MBAR_ARRIVE_NOINC(addr) \
    asm volatile("cp.async.mbarrier.arrive.noinc.shared.b64 [%0];" \
                 :: "r"((uint32_t)(addr)) : "memory")

#define MBARRIER_WAIT_PARITY(mbar_smem_addr, phase_parity) do { \
    uint32_t _mbar = (uint32_t)(mbar_smem_addr); \
    uint32_t _parity = (uint32_t)(phase_parity); \
    uint32_t _done; \
    asm volatile( \
        "{\n\t.reg .pred p;\n\t" \
        "mbarrier.try_wait.parity.acquire.cta.shared::cta.b64 p, [%1], %2;\n\t" \
        "selp.b32 %0, 1, 0, p;\n\t}" \
        : "=r"(_done) : "r"(_mbar), "r"(_parity) : "memory"); \
    if (!_done) { \
        asm volatile( \
            "{\n\t.reg .pred P1;\n\t" \
            "WAIT_LOOP_%=:\n\t" \
            "mbarrier.try_wait.parity.acquire.cta.shared::cta.b64 P1, [%0], %1, 0x989680;\n\t" \
            "@P1 bra.uni WAIT_DONE_%=;\n\t" \
            "bra.uni WAIT_LOOP_%=;\n\t" \
            "WAIT_DONE_%=:\n\t}" \
            :: "r"(_mbar), "r"(_parity) : "memory"); \
    } \
} while(0)

// elected single-lane wait + warp reconvergence
#define WARP_WAIT_PARITY(addr, parity) do { \
    if (elect_one()) { MBARRIER_WAIT_PARITY(addr, parity); } \
    __syncwarp(); \
} while (0)

__device__ __forceinline__ void ldmatrix_x4(uint32_t& r0, uint32_t& r1,
                                            uint32_t& r2, uint32_t& r3, uint32_t addr) {
    asm volatile("ldmatrix.sync.aligned.m8n8.x4.shared.b16 {%0,%1,%2,%3}, [%4];"
                 : "=r"(r0), "=r"(r1), "=r"(r2), "=r"(r3) : "r"(addr));
}

__device__ __forceinline__ void mma_16816(float* c, const uint32_t* a, const uint32_t* b) {
    asm volatile(
        "mma.sync.aligned.m16n8k16.row.col.f32.f16.f16.f32 "
        "{%0,%1,%2,%3}, {%4,%5,%6,%7}, {%8,%9}, {%0,%1,%2,%3};"
        : "+f"(c[0]), "+f"(c[1]), "+f"(c[2]), "+f"(c[3])
        : "r"(a[0]), "r"(a[1]), "r"(a[2]), "r"(a[3]), "r"(b[0]), "r"(b[1]));
}

// swizzle within a [rows][BK] fp16 tile, 128B rows: 16B chunk XOR (row & 7)
__device__ __forceinline__ uint32_t tile_off(int row, int chunk) {
    return (uint32_t)(row * 128 + ((chunk ^ (row & 7)) << 4));
}

// ------------------------- in-kernel x converter ---------------------------
// warp-granular work-steal: item s covers rows [(s&127)*64, +64) of k-chunk
// s>>7. Publishes g_flags[1+c] after each item (all-lane fence + elected add).
__device__ void convert_x_warp(const float4* __restrict__ x4,
                               uint2* __restrict__ xh2, int lane)
{
    for (;;) {
        int s = 0;
        if (lane == 0) s = atomicAdd(&g_flags[0], 1);
        s = __shfl_sync(0xFFFFFFFF, s, 0);
        if (s >= X_ITEMS) break;

        const int c  = s >> 7;
        const int rb = (s & 127) * 64;
        const int cbase = c * 16 + (lane & 15);
        const int rl = lane >> 4;            // 0/1

        #pragma unroll 1
        for (int p = 0; p < 32; p += 4) {
            float4 v[4];
            #pragma unroll
            for (int u = 0; u < 4; u++) {
                int r = rb + (p + u) * 2 + rl;
                v[u] = x4[(size_t)r * (K_DIM / 4) + cbase];
            }
            #pragma unroll
            for (int u = 0; u < 4; u++) {
                int r = rb + (p + u) * 2 + rl;
                __half2 h0 = __floats2half2_rn(v[u].x, v[u].y);
                __half2 h1 = __floats2half2_rn(v[u].z, v[u].w);
                uint2 o;
                o.x = *reinterpret_cast<uint32_t*>(&h0);
                o.y = *reinterpret_cast<uint32_t*>(&h1);
                xh2[(size_t)r * (K_DIM / 4) + cbase] = o;
            }
        }

        __threadfence();                     // all lanes: publish stores
        __syncwarp();
        if (lane == 0) atomicAdd(&g_flags[1 + c], 1);
    }
}

// ------------------------------ GEMM kernel --------------------------------
__global__ void __launch_bounds__(THREADS_ALL, 1) bgemm_mma_kernel(
    const float*  __restrict__ X,   // [M,K] fp32 (converted by warp 16)
    const __half* __restrict__ A,   // [M,K] fp16 (g_xh)
    const __half* __restrict__ B,   // [N,K] fp16 (g_wbt)
    float* __restrict__ out)
{
    extern __shared__ uint8_t smem_raw[];
    uint32_t raw = smem_u32(smem_raw);
    const uint32_t hdr   = (raw + 1023u) & ~1023u;
    const uint32_t tiles = hdr + 1024u;

    #define FULL_BAR(s)  (hdr + (uint32_t)(s) * 8u)
    #define EMPTY_BAR(s) (hdr + 64u + (uint32_t)(s) * 8u)

    const int tid  = threadIdx.x;
    const int wid  = tid >> 5;
    const int lane = tid & 31;

    if (tid == 0) {
        #pragma unroll
        for (int s = 0; s < STAGES; s++) {
            MBARRIER_INIT(FULL_BAR(s), GEMM_THREADS);
            MBARRIER_INIT(EMPTY_BAR(s), GEMM_WARPS);
        }
        asm volatile("fence.proxy.async.shared::cta;" ::: "memory");
    }
    __syncthreads();

    // warp 16: convert x, then exit
    if (wid == GEMM_WARPS) {
        convert_x_warp(reinterpret_cast<const float4*>(X),
                       reinterpret_cast<uint2*>(const_cast<__half*>(A)), lane);
        return;
    }

    const int m0 = blockIdx.x * BM;
    const int n0 = blockIdx.y * BN;

    const int warp_m = wid & 3;   // 4 warps over M: 32 rows each
    const int warp_n = wid >> 2;  // 4 warps over N: 64 cols each

    const int ld_row0  = tid >> 3;   // 0..63
    const int ld_chunk = tid & 7;    // 0..7

    auto load_stage = [&](int slot, int kt) {
        // gate on chunk kt converted (elected poll, warp reconverge)
        if (elect_one()) {
            while (ld_acquire_gpu(&g_flags[1 + kt]) < ITEMS_PER_CHK) {}
        }
        __syncwarp();

        const uint32_t sA = tiles + slot * STAGE_BYTES;
        const uint32_t sB = sA + A_TILE_BYTES;
        const int kcol = kt * BK + ld_chunk * 8;
        #pragma unroll
        for (int p = 0; p < 2; p++) {
            int row = ld_row0 + p * 64;
            cp_async_16(sA + tile_off(row, ld_chunk),
                        A + (size_t)(m0 + row) * K_DIM + kcol);
        }
        #pragma unroll
        for (int p = 0; p < 4; p++) {
            int row = ld_row0 + p * 64;
            cp_async_16(sB + tile_off(row, ld_chunk),
                        B + (size_t)(n0 + row) * K_DIM + kcol);
        }
        CPASYNC_MBAR_ARRIVE_NOINC(FULL_BAR(slot));
    };

    const int lrow = lane & 15;
    const int lsel = lane >> 4;

    uint32_t a_off[2], b_off[4];
    #pragma unroll
    for (int mi = 0; mi < 2; mi++)
        a_off[mi] = tile_off(warp_m * 32 + mi * 16 + lrow, lsel);
    #pragma unroll
    for (int nj = 0; nj < 4; nj++)
        b_off[nj] = tile_off(warp_n * 64 + nj * 16 + lrow, lsel);

    float acc[2][8][4];
    #pragma unroll
    for (int mi = 0; mi < 2; mi++)
        #pragma unroll
        for (int ni = 0; ni < 8; ni++)
            #pragma unroll
            for (int j = 0; j < 4; j++) acc[mi][ni][j] = 0.f;

    // prologue: fill stages 0..2
    #pragma unroll
    for (int s = 0; s < STAGES - 1; s++) {
        WARP_WAIT_PARITY(EMPTY_BAR(s), 1);
        load_stage(s, s);
    }

    for (int it = 0; it < NKI; it++) {
        const int s = it & 3;
        const uint32_t sA = tiles + s * STAGE_BYTES;
        const uint32_t sB = sA + A_TILE_BYTES;

        WARP_WAIT_PARITY(FULL_BAR(s), (it >> 2) & 1);

        #pragma unroll
        for (int kk = 0; kk < BK / 16; kk++) {
            const uint32_t kx = (uint32_t)kk << 5;

            uint32_t a[2][4];
            #pragma unroll
            for (int mi = 0; mi < 2; mi++)
                ldmatrix_x4(a[mi][0], a[mi][1], a[mi][2], a[mi][3],
                            (sA + a_off[mi]) ^ kx);
            uint32_t b[8][2];
            #pragma unroll
            for (int nj = 0; nj < 4; nj++) {
                uint32_t r0, r1, r2, r3;
                ldmatrix_x4(r0, r1, r2, r3, (sB + b_off[nj]) ^ kx);
                b[nj * 2 + 0][0] = r0; b[nj * 2 + 1][0] = r1;
                b[nj * 2 + 0][1] = r2; b[nj * 2 + 1][1] = r3;
            }

            if (kk == BK / 16 - 1) {
                __syncwarp();
                if (elect_one()) MBARRIER_ARRIVE(EMPTY_BAR(s));
            }

            #pragma unroll
            for (int mi = 0; mi < 2; mi++)
                #pragma unroll
                for (int ni = 0; ni < 8; ni++)
                    mma_16816(acc[mi][ni], a[mi], b[ni]);
        }

        const int kt = it + STAGES - 1;
        if (kt < NKI) {
            const int ps = kt & 3;
            WARP_WAIT_PARITY(EMPTY_BAR(ps), ((kt >> 2) & 1) ^ 1);
            load_stage(ps, kt);
        }
    }

    // ------------------------------ epilogue -------------------------------
    const int tq = lane >> 2;
    const int tp = lane & 3;
    #pragma unroll
    for (int mi = 0; mi < 2; mi++) {
        #pragma unroll
        for (int ni = 0; ni < 8; ni++) {
            int r = m0 + warp_m * 32 + mi * 16 + tq;
            int c = n0 + warp_n * 64 + ni * 8 + tp * 2;
            float2 v0 = make_float2(acc[mi][ni][0], acc[mi][ni][1]);
            float2 v1 = make_float2(acc[mi][ni][2], acc[mi][ni][3]);
            *reinterpret_cast<float2*>(out + (size_t)r * N_DIM + c) = v0;
            *reinterpret_cast<float2*>(out + (size_t)(r + 8) * N_DIM + c) = v1;
        }
    }
}

// ------------------------------- host side --------------------------------
extern "C" void kernel_launch(void* const* d_in, const int* in_sizes, int n_in,
                              void* d_out, int out_size)
{
    const float* x = (const float*)d_in[0];
    const float* w = (const float*)d_in[1];
    float* out = (float*)d_out;

    void *xh_ptr = nullptr, *wbt_ptr = nullptr, *flags_ptr = nullptr;
    cudaGetSymbolAddress(&xh_ptr, g_xh);
    cudaGetSymbolAddress(&wbt_ptr, g_wbt);
    cudaGetSymbolAddress(&flags_ptr, g_flags);

    // reset work-steal + chunk flags (converts re-run every call)
    cudaMemsetAsync(flags_ptr, 0, sizeof(int) * (1 + NKI));

    // w convert (needs transpose) stays serial: ~16us
    {
        dim3 gw(N_DIM / 64, K_DIM / 64);
        cvt_w_kernel<<<gw, 256>>>(w, (__half*)wbt_ptr);
    }

    cudaFuncSetAttribute(bgemm_mma_kernel,
                         cudaFuncAttributeMaxDynamicSharedMemorySize, SMEM_DYN);

    dim3 grid(M_DIM / BM, N_DIM / BN);  // (64, 16)
    bgemm_mma_kernel<<<grid, THREADS_ALL, SMEM_DYN>>>(
        x, (const __half*)xh_ptr, (const __half*)wbt_ptr, out);
}